// round 5
// baseline (speedup 1.0000x reference)
#include <cuda_runtime.h>
#include <math.h>

// Problem constants
#define NN 50000
#define EE 800000
#define NE 850000      // EE + NN self loops
#define FIN 32
#define CDIM 16
#define DIN 48
#define CC 64
#define H0 2

// ---------------- device scratch (allocation-free rule: __device__ globals) --------
__device__ float g_h0[NN * 128];      // layer0 node features [N,2,64]
__device__ float g_as0[NN * 2];
__device__ float g_ad0[NN * 2];
__device__ float g_den0[NN * 2];      // unnormalized softmax denominators
__device__ float g_agg0[NN * 128];    // unnormalized aggregated messages
__device__ float g_h1[NN * 64];
__device__ float g_as1[NN];
__device__ float g_ad1[NN];
__device__ float g_den1[NN];
__device__ float g_wa0[DIN * 4];      // folded attention weights: [k][c], c: src_h0,src_h1,dst_h0,dst_h1

// vector reduction-add to global (sm_90+)
__device__ __forceinline__ void red_add_v4(float* addr, float a, float b, float c, float d) {
    asm volatile("red.global.add.v4.f32 [%0], {%1,%2,%3,%4};"
                 :: "l"(addr), "f"(a), "f"(b), "f"(c), "f"(d) : "memory");
}

// ---------------- init: zero agg0, den0, den1, out ---------------------------------
__global__ void kinit(float* __restrict__ out) {
    int i = blockIdx.x * blockDim.x + threadIdx.x;
    int stride = gridDim.x * blockDim.x;
    float4 z = make_float4(0.f, 0.f, 0.f, 0.f);
    float4* a4 = (float4*)g_agg0;
    float4* o4 = (float4*)out;
    for (int k = i; k < NN * 32; k += stride) a4[k] = z;
    for (int k = i; k < NN * 16; k += stride) o4[k] = z;
    for (int k = i; k < NN * 2; k += stride) g_den0[k] = 0.f;
    for (int k = i; k < NN; k += stride) g_den1[k] = 0.f;
}

// ---------------- kprep: fold attention vectors through W0 -------------------------
// g_wa0[k*4+c] = sum_j W0[k, h*64+j] * a[h][j],  c in {src_h0, src_h1, dst_h0, dst_h1}
__global__ void kprep(const float* __restrict__ W0, const float* __restrict__ as0,
                      const float* __restrict__ ad0) {
    int t = threadIdx.x;              // 0..191
    if (t >= DIN * 4) return;
    int k = t >> 2, c = t & 3;
    int h = c & 1;
    const float* a = (c < 2) ? as0 : ad0;
    float s = 0.f;
    #pragma unroll
    for (int j = 0; j < 64; ++j) s += W0[k * 128 + h * 64 + j] * a[h * 64 + j];
    g_wa0[k * 4 + c] = s;
}

// ---------------- K1: h0 = concat(base, emb[cid]) @ W0 ; folded as0/ad0 ------------
#define K1_NPB 64
__global__ void __launch_bounds__(128) k1(const float* __restrict__ x,
                                          const float* __restrict__ emb,
                                          const float* __restrict__ W0) {
    __shared__ __align__(16) float sIn[8][52];   // stride 52: conflict-free & 16B-aligned rows
    __shared__ float swa[DIN * 4];
    int j = threadIdx.x;              // output column 0..127
    float wreg[48];
    #pragma unroll
    for (int k = 0; k < 48; ++k) wreg[k] = W0[k * 128 + j];
    for (int t = j; t < DIN * 4; t += 128) swa[t] = g_wa0[t];

    int base = blockIdx.x * K1_NPB;
    for (int b = 0; b < K1_NPB / 8; ++b) {
        int n0 = base + b * 8;
        __syncthreads();
        // cooperative load of 8 node inputs (48 each)
        #pragma unroll
        for (int r = 0; r < 3; ++r) {
            int s = j + r * 128;      // 0..383
            int m = s / 48, k = s % 48;
            int n = n0 + m;
            float v = 0.f;
            if (n < NN) {
                if (k < FIN) v = x[n * 33 + k];
                else {
                    int cid = (int)x[n * 33 + FIN];
                    v = emb[cid * CDIM + (k - FIN)];
                }
            }
            sIn[m][k] = v;
        }
        __syncthreads();

        float acc[8];
        #pragma unroll
        for (int m = 0; m < 8; ++m) {
            float a = 0.f;
            #pragma unroll
            for (int q = 0; q < 12; ++q) {
                float4 v = *(const float4*)&sIn[m][q * 4];
                a += v.x * wreg[q * 4] + v.y * wreg[q * 4 + 1]
                   + v.z * wreg[q * 4 + 2] + v.w * wreg[q * 4 + 3];
            }
            acc[m] = a;
        }
        #pragma unroll
        for (int m = 0; m < 8; ++m) {
            int n = n0 + m;
            if (n < NN) g_h0[n * 128 + j] = acc[m];
        }
        // folded attention scalars: warp 0, lane = m*4 + c
        if (j < 32) {
            int m = j >> 2, c = j & 3;
            int n = n0 + m;
            if (n < NN) {
                float s = 0.f;
                #pragma unroll
                for (int k = 0; k < 48; ++k) s += sIn[m][k] * swa[k * 4 + c];
                if (c < 2) g_as0[n * 2 + c] = s;
                else       g_ad0[n * 2 + (c & 1)] = s;
            }
        }
    }
}

// ---------------- K2: fused layer0 edge pass (warp per edge) -----------------------
// agg0[dst] += ex * h0[src];  den0[dst] += ex   (normalize later in k4)
__global__ void k2(const int* __restrict__ ei) {
    int gid = blockIdx.x * blockDim.x + threadIdx.x;
    int e = gid >> 5;
    if (e >= NE) return;
    int lane = gid & 31;
    int src, dst;
    if (e < EE) { src = ei[e]; dst = ei[EE + e]; }
    else        { src = dst = e - EE; }
    int head = lane >> 4;             // lanes 0-15: head0, 16-31: head1
    float v = g_as0[src * 2 + head] + g_ad0[dst * 2 + head];
    v = v > 0.f ? v : 0.2f * v;
    float ex = __expf(v);
    const float4 h = *(const float4*)(g_h0 + src * 128 + lane * 4);
    red_add_v4(g_agg0 + dst * 128 + lane * 4,
               ex * h.x, ex * h.y, ex * h.z, ex * h.w);
    if ((lane & 15) == 0) atomicAdd(&g_den0[dst * 2 + head], ex);
}

// ---------------- K4: normalize + mean heads + b0, LN, ELU, GEMM W1, alphas --------
#define NPB4 32
__device__ __forceinline__ float2 gsum64x2(float a, float b, float* s4, int jj) {
    #pragma unroll
    for (int o = 16; o > 0; o >>= 1) {
        a += __shfl_xor_sync(0xffffffffu, a, o);
        b += __shfl_xor_sync(0xffffffffu, b, o);
    }
    if ((jj & 31) == 0) { s4[jj >> 5] = a; s4[2 + (jj >> 5)] = b; }
    __syncthreads();
    float2 r = make_float2(s4[0] + s4[1], s4[2] + s4[3]);
    __syncthreads();
    return r;
}

__global__ void __launch_bounds__(256) k4(const float* __restrict__ b0,
                   const float* __restrict__ lng, const float* __restrict__ lnb,
                   const float* __restrict__ W1, const float* __restrict__ a_s1,
                   const float* __restrict__ a_d1) {
    __shared__ __align__(16) float sX[4][64];
    __shared__ float sred[4][4];
    __shared__ float sinv[4][2];
    int tid = threadIdx.x;            // 256 threads: 4 groups of 64
    int gg = tid >> 6, jj = tid & 63;
    float wreg[64];
    #pragma unroll
    for (int t = 0; t < 64; ++t) wreg[t] = W1[t * 64 + jj];
    float aS = a_s1[jj], aD = a_d1[jj];
    float bb = b0[jj], g = lng[jj], be = lnb[jj];

    int base = blockIdx.x * NPB4;
    for (int it = 0; it < NPB4 / 4; ++it) {
        int n = base + it * 4 + gg;
        bool valid = (n < NN);
        int nn = valid ? n : 0;
        if (jj < 2) sinv[gg][jj] = 1.0f / g_den0[nn * 2 + jj];
        __syncthreads();
        float y = 0.f;
        if (valid)
            y = 0.5f * (g_agg0[nn * 128 + jj] * sinv[gg][0]
                      + g_agg0[nn * 128 + 64 + jj] * sinv[gg][1]) + bb;
        float2 r = gsum64x2(y, y * y, sred[gg], jj);
        float mu = r.x * (1.f / 64.f);
        float var = r.y * (1.f / 64.f) - mu * mu;
        float xn = (y - mu) * rsqrtf(var + 1e-5f) * g + be;
        float ev = xn > 0.f ? xn : expm1f(xn);
        sX[gg][jj] = ev;
        __syncthreads();
        float acc = 0.f;
        #pragma unroll
        for (int q = 0; q < 16; ++q) {
            float4 v = *(const float4*)&sX[gg][q * 4];
            acc += v.x * wreg[q * 4] + v.y * wreg[q * 4 + 1]
                 + v.z * wreg[q * 4 + 2] + v.w * wreg[q * 4 + 3];
        }
        float2 r2 = gsum64x2(acc * aS, acc * aD, sred[gg], jj);
        if (valid) {
            g_h1[n * 64 + jj] = acc;
            if (jj == 0) { g_as1[n] = r2.x; g_ad1[n] = r2.y; }
        }
        __syncthreads();
    }
}

// ---------------- K5: fused layer1 edge pass (16 lanes per edge) -------------------
// out[dst] += ex * h1[src];  den1[dst] += ex
__global__ void k5(const int* __restrict__ ei, float* __restrict__ out) {
    int gid = blockIdx.x * blockDim.x + threadIdx.x;
    int e = gid >> 4;
    if (e >= NE) return;
    int l = gid & 15;
    int src, dst;
    if (e < EE) { src = ei[e]; dst = ei[EE + e]; }
    else        { src = dst = e - EE; }
    float v = g_as1[src] + g_ad1[dst];
    v = v > 0.f ? v : 0.2f * v;
    float ex = __expf(v);
    const float4 h = *(const float4*)(g_h1 + src * 64 + l * 4);
    red_add_v4(out + dst * 64 + l * 4,
               ex * h.x, ex * h.y, ex * h.z, ex * h.w);
    if (l == 0) atomicAdd(&g_den1[dst], ex);
}

// ---------------- knorm: out = out/den1 + b1 (warp per node) -----------------------
__global__ void knorm(float* __restrict__ out, const float* __restrict__ b1) {
    int gid = blockIdx.x * blockDim.x + threadIdx.x;
    int w = gid >> 5;
    if (w >= NN) return;
    int lane = gid & 31;
    float inv;
    if (lane == 0) inv = 1.0f / g_den1[w];
    inv = __shfl_sync(0xffffffffu, inv, 0);
    float2 v = *(float2*)(out + w * 64 + lane * 2);
    float2 bb = *(const float2*)(b1 + lane * 2);
    v.x = v.x * inv + bb.x;
    v.y = v.y * inv + bb.y;
    *(float2*)(out + w * 64 + lane * 2) = v;
}

// ---------------- launch -----------------------------------------------------------
extern "C" void kernel_launch(void* const* d_in, const int* in_sizes, int n_in,
                              void* d_out, int out_size) {
    const float* x      = (const float*)d_in[0];
    const int*   ei     = (const int*)  d_in[1];
    const float* emb    = (const float*)d_in[2];
    const float* W0     = (const float*)d_in[3];
    const float* a_src0 = (const float*)d_in[4];
    const float* a_dst0 = (const float*)d_in[5];
    const float* b0     = (const float*)d_in[6];
    const float* ln_g   = (const float*)d_in[7];
    const float* ln_b   = (const float*)d_in[8];
    const float* W1     = (const float*)d_in[9];
    const float* a_src1 = (const float*)d_in[10];
    const float* a_dst1 = (const float*)d_in[11];
    const float* b1     = (const float*)d_in[12];
    float* out = (float*)d_out;

    kinit<<<2048, 256>>>(out);
    kprep<<<1, 192>>>(W0, a_src0, a_dst0);
    k1<<<(NN + K1_NPB - 1) / K1_NPB, 128>>>(x, emb, W0);
    k2<<<(NE * 32 + 255) / 256, 256>>>(ei);
    k4<<<(NN + NPB4 - 1) / NPB4, 256>>>(b0, ln_g, ln_b, W1, a_src1, a_dst1);
    k5<<<(NE * 16 + 255) / 256, 256>>>(ei, out);
    knorm<<<(NN * 32 + 255) / 256, 256>>>(out, b1);
}

// round 9
// speedup vs baseline: 1.3876x; 1.3876x over previous
#include <cuda_runtime.h>
#include <math.h>

// Problem constants
#define NN 50000
#define EE 800000
#define NE 850000      // EE + NN self loops
#define FIN 32
#define CDIM 16
#define DIN 48
#define CC 64
#define H0 2

// ---------------- device scratch (allocation-free rule: __device__ globals) --------
__device__ float g_h0[NN * 128];      // layer0 node features [N,2,64]
__device__ float g_as0[NN * 2];
__device__ float g_ad0[NN * 2];
__device__ float g_den0[NN * 2];      // unnormalized softmax denominators
__device__ float g_agg0[NN * 128];    // unnormalized aggregated messages
__device__ float g_h1[NN * 64];
__device__ float g_as1[NN];
__device__ float g_ad1[NN];
__device__ float g_den1[NN];
__device__ float g_wa0[DIN * 4];      // folded attention weights

// vector reduction-add to global (sm_90+)
__device__ __forceinline__ void red_add_v4(float* addr, float a, float b, float c, float d) {
    asm volatile("red.global.add.v4.f32 [%0], {%1,%2,%3,%4};"
                 :: "l"(addr), "f"(a), "f"(b), "f"(c), "f"(d) : "memory");
}
__device__ __forceinline__ void red_add_v2(float* addr, float a, float b) {
    asm volatile("red.global.add.v2.f32 [%0], {%1,%2};"
                 :: "l"(addr), "f"(a), "f"(b) : "memory");
}

// ---------------- init: zero agg0, den0, den1, out ---------------------------------
__global__ void kinit(float* __restrict__ out) {
    int i = blockIdx.x * blockDim.x + threadIdx.x;
    int stride = gridDim.x * blockDim.x;
    float4 z = make_float4(0.f, 0.f, 0.f, 0.f);
    float4* a4 = (float4*)g_agg0;
    float4* o4 = (float4*)out;
    for (int k = i; k < NN * 32; k += stride) a4[k] = z;
    for (int k = i; k < NN * 16; k += stride) o4[k] = z;
    for (int k = i; k < NN * 2; k += stride) g_den0[k] = 0.f;
    for (int k = i; k < NN; k += stride) g_den1[k] = 0.f;
}

// ---------------- kprep: fold attention vectors through W0 -------------------------
__global__ void kprep(const float* __restrict__ W0, const float* __restrict__ as0,
                      const float* __restrict__ ad0) {
    int t = threadIdx.x;              // 0..191
    if (t >= DIN * 4) return;
    int k = t >> 2, c = t & 3;
    int h = c & 1;
    const float* a = (c < 2) ? as0 : ad0;
    float s = 0.f;
    #pragma unroll
    for (int j = 0; j < 64; ++j) s += W0[k * 128 + h * 64 + j] * a[h * 64 + j];
    g_wa0[k * 4 + c] = s;
}

// ---------------- K1: h0 = concat(base, emb[cid]) @ W0 ; folded as0/ad0 ------------
#define K1_NPB 64
__global__ void __launch_bounds__(128) k1(const float* __restrict__ x,
                                          const float* __restrict__ emb,
                                          const float* __restrict__ W0) {
    __shared__ __align__(16) float sIn[8][52];
    __shared__ float swa[DIN * 4];
    int j = threadIdx.x;              // output column 0..127
    float wreg[48];
    #pragma unroll
    for (int k = 0; k < 48; ++k) wreg[k] = W0[k * 128 + j];
    for (int t = j; t < DIN * 4; t += 128) swa[t] = g_wa0[t];

    int base = blockIdx.x * K1_NPB;
    for (int b = 0; b < K1_NPB / 8; ++b) {
        int n0 = base + b * 8;
        __syncthreads();
        #pragma unroll
        for (int r = 0; r < 3; ++r) {
            int s = j + r * 128;      // 0..383
            int m = s / 48, k = s % 48;
            int n = n0 + m;
            float v = 0.f;
            if (n < NN) {
                if (k < FIN) v = x[n * 33 + k];
                else {
                    int cid = (int)x[n * 33 + FIN];
                    v = emb[cid * CDIM + (k - FIN)];
                }
            }
            sIn[m][k] = v;
        }
        __syncthreads();

        float acc[8];
        #pragma unroll
        for (int m = 0; m < 8; ++m) {
            float a = 0.f;
            #pragma unroll
            for (int q = 0; q < 12; ++q) {
                float4 v = *(const float4*)&sIn[m][q * 4];
                a += v.x * wreg[q * 4] + v.y * wreg[q * 4 + 1]
                   + v.z * wreg[q * 4 + 2] + v.w * wreg[q * 4 + 3];
            }
            acc[m] = a;
        }
        #pragma unroll
        for (int m = 0; m < 8; ++m) {
            int n = n0 + m;
            if (n < NN) g_h0[n * 128 + j] = acc[m];
        }
        if (j < 32) {
            int m = j >> 2, c = j & 3;
            int n = n0 + m;
            if (n < NN) {
                float s = 0.f;
                #pragma unroll
                for (int k = 0; k < 48; ++k) s += sIn[m][k] * swa[k * 4 + c];
                if (c < 2) g_as0[n * 2 + c] = s;
                else       g_ad0[n * 2 + (c & 1)] = s;
            }
        }
    }
}

// ---------------- K2: fused layer0 edge pass (warp per edge, exp once per edge) ----
// agg0[dst] += ex * h0[src];  den0[dst] += ex  (normalize later in k4)
__global__ void __launch_bounds__(256) k2(const int* __restrict__ ei) {
    int gid = blockIdx.x * blockDim.x + threadIdx.x;
    int e = gid >> 5;
    if (e >= NE) return;
    int lane = gid & 31;
    int src, dst;
    if (e < EE) { src = ei[e]; dst = ei[EE + e]; }
    else        { src = dst = e - EE; }
    float ex0 = 0.f, ex1 = 0.f;
    if (lane == 0) {
        float2 a = *(const float2*)(g_as0 + src * 2);
        float2 b = *(const float2*)(g_ad0 + dst * 2);
        float v0 = a.x + b.x;  v0 = v0 > 0.f ? v0 : 0.2f * v0;
        float v1 = a.y + b.y;  v1 = v1 > 0.f ? v1 : 0.2f * v1;
        ex0 = __expf(v0);
        ex1 = __expf(v1);
        red_add_v2(g_den0 + dst * 2, ex0, ex1);
    }
    float e0 = __shfl_sync(0xffffffffu, ex0, 0);
    float e1 = __shfl_sync(0xffffffffu, ex1, 0);
    float ex = (lane < 16) ? e0 : e1;     // lanes 0-15: head0, 16-31: head1
    const float4 h = *(const float4*)(g_h0 + src * 128 + lane * 4);
    red_add_v4(g_agg0 + dst * 128 + lane * 4,
               ex * h.x, ex * h.y, ex * h.z, ex * h.w);
}

// ---------------- K4: normalize + mean heads + b0, LN, ELU, GEMM W1, alphas --------
#define NPB4 32
__device__ __forceinline__ float2 gsum64x2(float a, float b, float* s4, int jj) {
    #pragma unroll
    for (int o = 16; o > 0; o >>= 1) {
        a += __shfl_xor_sync(0xffffffffu, a, o);
        b += __shfl_xor_sync(0xffffffffu, b, o);
    }
    if ((jj & 31) == 0) { s4[jj >> 5] = a; s4[2 + (jj >> 5)] = b; }
    __syncthreads();
    float2 r = make_float2(s4[0] + s4[1], s4[2] + s4[3]);
    __syncthreads();
    return r;
}

__global__ void __launch_bounds__(256) k4(const float* __restrict__ b0,
                   const float* __restrict__ lng, const float* __restrict__ lnb,
                   const float* __restrict__ W1, const float* __restrict__ a_s1,
                   const float* __restrict__ a_d1) {
    __shared__ __align__(16) float sX[4][64];
    __shared__ float sred[4][4];
    __shared__ float sinv[4][2];
    int tid = threadIdx.x;            // 256 threads: 4 groups of 64
    int gg = tid >> 6, jj = tid & 63;
    float wreg[64];
    #pragma unroll
    for (int t = 0; t < 64; ++t) wreg[t] = W1[t * 64 + jj];
    float aS = a_s1[jj], aD = a_d1[jj];
    float bb = b0[jj], g = lng[jj], be = lnb[jj];

    int base = blockIdx.x * NPB4;
    for (int it = 0; it < NPB4 / 4; ++it) {
        int n = base + it * 4 + gg;
        bool valid = (n < NN);
        int nn = valid ? n : 0;
        if (jj < 2) sinv[gg][jj] = 1.0f / g_den0[nn * 2 + jj];
        __syncthreads();
        float y = 0.f;
        if (valid)
            y = 0.5f * (g_agg0[nn * 128 + jj] * sinv[gg][0]
                      + g_agg0[nn * 128 + 64 + jj] * sinv[gg][1]) + bb;
        float2 r = gsum64x2(y, y * y, sred[gg], jj);
        float mu = r.x * (1.f / 64.f);
        float var = r.y * (1.f / 64.f) - mu * mu;
        float xn = (y - mu) * rsqrtf(var + 1e-5f) * g + be;
        float ev = xn > 0.f ? xn : expm1f(xn);
        sX[gg][jj] = ev;
        __syncthreads();
        float acc = 0.f;
        #pragma unroll
        for (int q = 0; q < 16; ++q) {
            float4 v = *(const float4*)&sX[gg][q * 4];
            acc += v.x * wreg[q * 4] + v.y * wreg[q * 4 + 1]
                 + v.z * wreg[q * 4 + 2] + v.w * wreg[q * 4 + 3];
        }
        float2 r2 = gsum64x2(acc * aS, acc * aD, sred[gg], jj);
        if (valid) {
            g_h1[n * 64 + jj] = acc;
            if (jj == 0) { g_as1[n] = r2.x; g_ad1[n] = r2.y; }
        }
        __syncthreads();
    }
}

// ---------------- K5: fused layer1 edge pass (16 lanes/edge, 2 edges/warp) ---------
// out[dst] += ex * h1[src];  den1[dst] += ex
__global__ void __launch_bounds__(256) k5(const int* __restrict__ ei, float* __restrict__ out) {
    int gid = blockIdx.x * blockDim.x + threadIdx.x;
    int w = gid >> 5;
    int lane = gid & 31;
    int sub = lane >> 4;              // which edge of the pair
    int l = lane & 15;
    int e = w * 2 + sub;
    bool valid = (e < NE);
    int src = 0, dst = 0;
    if (valid) {
        if (e < EE) { src = ei[e]; dst = ei[EE + e]; }
        else        { src = dst = e - EE; }
    }
    float ex = 0.f;
    if (valid && l == 0) {
        float v = g_as1[src] + g_ad1[dst];
        v = v > 0.f ? v : 0.2f * v;
        ex = __expf(v);
        atomicAdd(&g_den1[dst], ex);
    }
    ex = __shfl_sync(0xffffffffu, ex, sub << 4);
    if (!valid) return;
    const float4 h = *(const float4*)(g_h1 + src * 64 + l * 4);
    red_add_v4(out + dst * 64 + l * 4,
               ex * h.x, ex * h.y, ex * h.z, ex * h.w);
}

// ---------------- knorm: out = out/den1 + b1 (warp per node) -----------------------
__global__ void knorm(float* __restrict__ out, const float* __restrict__ b1) {
    int gid = blockIdx.x * blockDim.x + threadIdx.x;
    int w = gid >> 5;
    if (w >= NN) return;
    int lane = gid & 31;
    float inv;
    if (lane == 0) inv = 1.0f / g_den1[w];
    inv = __shfl_sync(0xffffffffu, inv, 0);
    float2 v = *(float2*)(out + w * 64 + lane * 2);
    float2 bb = *(const float2*)(b1 + lane * 2);
    v.x = v.x * inv + bb.x;
    v.y = v.y * inv + bb.y;
    *(float2*)(out + w * 64 + lane * 2) = v;
}

// ---------------- launch -----------------------------------------------------------
extern "C" void kernel_launch(void* const* d_in, const int* in_sizes, int n_in,
                              void* d_out, int out_size) {
    const float* x      = (const float*)d_in[0];
    const int*   ei     = (const int*)  d_in[1];
    const float* emb    = (const float*)d_in[2];
    const float* W0     = (const float*)d_in[3];
    const float* a_src0 = (const float*)d_in[4];
    const float* a_dst0 = (const float*)d_in[5];
    const float* b0     = (const float*)d_in[6];
    const float* ln_g   = (const float*)d_in[7];
    const float* ln_b   = (const float*)d_in[8];
    const float* W1     = (const float*)d_in[9];
    const float* a_src1 = (const float*)d_in[10];
    const float* a_dst1 = (const float*)d_in[11];
    const float* b1     = (const float*)d_in[12];
    float* out = (float*)d_out;

    kinit<<<2048, 256>>>(out);
    kprep<<<1, 192>>>(W0, a_src0, a_dst0);
    k1<<<(NN + K1_NPB - 1) / K1_NPB, 128>>>(x, emb, W0);
    k2<<<(NE * 32 + 255) / 256, 256>>>(ei);
    k4<<<(NN + NPB4 - 1) / NPB4, 256>>>(b0, ln_g, ln_b, W1, a_src1, a_dst1);
    k5<<<((NE + 1) / 2 * 32 + 255) / 256, 256>>>(ei, out);
    knorm<<<(NN * 32 + 255) / 256, 256>>>(out, b1);
}

// round 10
// speedup vs baseline: 1.5711x; 1.1323x over previous
#include <cuda_runtime.h>
#include <math.h>

// Problem constants
#define NN 50000
#define EE 800000
#define NE 850000      // EE + NN self loops
#define FIN 32
#define CDIM 16
#define DIN 48
#define CC 64
#define H0 2

// ---------------- device scratch (allocation-free rule: __device__ globals) --------
__device__ float g_h0[NN * 128];      // layer0 node features [N,2,64]
__device__ float g_as0[NN * 2];
__device__ float g_ad0[NN * 2];
__device__ float g_agg0[NN * 128];    // normalized aggregated messages (written once)
__device__ float g_h1[NN * 64];
__device__ float g_as1[NN];
__device__ float g_ad1[NN];
__device__ float g_wa0[DIN * 4];      // folded attention weights
// CSR build scratch
__device__ int g_cnt[NN];
__device__ int g_off[NN + 1];
__device__ int g_cur[NN];
__device__ int g_srcs[NE];

// ---------------- CSR build: zero counters ----------------------------------------
__global__ void kzero() {
    int i = blockIdx.x * blockDim.x + threadIdx.x;
    if (i < NN) g_cnt[i] = 0;
}

// ---------------- CSR build: histogram of dst -------------------------------------
__global__ void khist(const int* __restrict__ ei) {
    int e = blockIdx.x * blockDim.x + threadIdx.x;
    if (e >= NE) return;
    int dst = (e < EE) ? ei[EE + e] : (e - EE);
    atomicAdd(&g_cnt[dst], 1);
}

// ---------------- CSR build: exclusive scan (single block, 1024 threads) ----------
__global__ void __launch_bounds__(1024) kscan() {
    __shared__ int spart[1024];
    const int CH = (NN + 1023) / 1024;   // 49
    int t = threadIdx.x;
    int base = t * CH;
    int sum = 0;
    for (int i = 0; i < CH; ++i) {
        int b = base + i;
        if (b < NN) sum += g_cnt[b];
    }
    spart[t] = sum;
    __syncthreads();
    for (int o = 1; o < 1024; o <<= 1) {
        int v = (t >= o) ? spart[t - o] : 0;
        __syncthreads();
        spart[t] += v;
        __syncthreads();
    }
    int run = spart[t] - sum;           // exclusive prefix of this thread's chunk
    for (int i = 0; i < CH; ++i) {
        int b = base + i;
        if (b < NN) {
            g_off[b] = run;
            g_cur[b] = run;
            run += g_cnt[b];
        }
    }
    if (t == 1023) g_off[NN] = spart[1023];
}

// ---------------- CSR build: scatter src ids --------------------------------------
__global__ void kscatter(const int* __restrict__ ei) {
    int e = blockIdx.x * blockDim.x + threadIdx.x;
    if (e >= NE) return;
    int src, dst;
    if (e < EE) { src = ei[e]; dst = ei[EE + e]; }
    else        { src = dst = e - EE; }
    int pos = atomicAdd(&g_cur[dst], 1);
    g_srcs[pos] = src;
}

// ---------------- kprep: fold attention vectors through W0 -------------------------
__global__ void kprep(const float* __restrict__ W0, const float* __restrict__ as0,
                      const float* __restrict__ ad0) {
    int t = threadIdx.x;              // 0..191
    if (t >= DIN * 4) return;
    int k = t >> 2, c = t & 3;
    int h = c & 1;
    const float* a = (c < 2) ? as0 : ad0;
    float s = 0.f;
    #pragma unroll
    for (int j = 0; j < 64; ++j) s += W0[k * 128 + h * 64 + j] * a[h * 64 + j];
    g_wa0[k * 4 + c] = s;
}

// ---------------- K1: h0 = concat(base, emb[cid]) @ W0 ; folded as0/ad0 ------------
#define K1_NPB 64
__global__ void __launch_bounds__(128) k1(const float* __restrict__ x,
                                          const float* __restrict__ emb,
                                          const float* __restrict__ W0) {
    __shared__ __align__(16) float sIn[8][52];
    __shared__ float swa[DIN * 4];
    int j = threadIdx.x;              // output column 0..127
    float wreg[48];
    #pragma unroll
    for (int k = 0; k < 48; ++k) wreg[k] = W0[k * 128 + j];
    for (int t = j; t < DIN * 4; t += 128) swa[t] = g_wa0[t];

    int base = blockIdx.x * K1_NPB;
    for (int b = 0; b < K1_NPB / 8; ++b) {
        int n0 = base + b * 8;
        __syncthreads();
        #pragma unroll
        for (int r = 0; r < 3; ++r) {
            int s = j + r * 128;      // 0..383
            int m = s / 48, k = s % 48;
            int n = n0 + m;
            float v = 0.f;
            if (n < NN) {
                if (k < FIN) v = x[n * 33 + k];
                else {
                    int cid = (int)x[n * 33 + FIN];
                    v = emb[cid * CDIM + (k - FIN)];
                }
            }
            sIn[m][k] = v;
        }
        __syncthreads();

        float acc[8];
        #pragma unroll
        for (int m = 0; m < 8; ++m) {
            float a = 0.f;
            #pragma unroll
            for (int q = 0; q < 12; ++q) {
                float4 v = *(const float4*)&sIn[m][q * 4];
                a += v.x * wreg[q * 4] + v.y * wreg[q * 4 + 1]
                   + v.z * wreg[q * 4 + 2] + v.w * wreg[q * 4 + 3];
            }
            acc[m] = a;
        }
        #pragma unroll
        for (int m = 0; m < 8; ++m) {
            int n = n0 + m;
            if (n < NN) g_h0[n * 128 + j] = acc[m];
        }
        if (j < 32) {
            int m = j >> 2, c = j & 3;
            int n = n0 + m;
            if (n < NN) {
                float s = 0.f;
                #pragma unroll
                for (int k = 0; k < 48; ++k) s += sIn[m][k] * swa[k * 4 + c];
                if (c < 2) g_as0[n * 2 + c] = s;
                else       g_ad0[n * 2 + (c & 1)] = s;
            }
        }
    }
}

// ---------------- kagg0: layer0 aggregation, warp per dst node --------------------
// acc = sum_e ex_e * h0[src_e]; write agg0 = acc / den (normalized, per head)
__global__ void __launch_bounds__(256) kagg0() {
    int w = (blockIdx.x * blockDim.x + threadIdx.x) >> 5;
    if (w >= NN) return;
    int lane = threadIdx.x & 31;
    int start = g_off[w], end = g_off[w + 1];
    float2 ad = *(const float2*)(g_ad0 + w * 2);
    float4 acc = make_float4(0.f, 0.f, 0.f, 0.f);
    float d0 = 0.f, d1 = 0.f;
    for (int i = start; i < end; i += 32) {
        int idx = i + lane;
        int s = 0;
        float ex0 = 0.f, ex1 = 0.f;
        if (idx < end) {
            s = g_srcs[idx];
            float2 a = *(const float2*)(g_as0 + s * 2);
            float v0 = a.x + ad.x;  v0 = v0 > 0.f ? v0 : 0.2f * v0;
            float v1 = a.y + ad.y;  v1 = v1 > 0.f ? v1 : 0.2f * v1;
            ex0 = __expf(v0);
            ex1 = __expf(v1);
        }
        d0 += ex0;
        d1 += ex1;
        int cnt = min(32, end - i);
        for (int t = 0; t < cnt; ++t) {
            int sb = __shfl_sync(0xffffffffu, s, t);
            float e0 = __shfl_sync(0xffffffffu, ex0, t);
            float e1 = __shfl_sync(0xffffffffu, ex1, t);
            float exm = (lane < 16) ? e0 : e1;   // lanes 0-15: head0, 16-31: head1
            const float4 h = *(const float4*)(g_h0 + sb * 128 + lane * 4);
            acc.x += exm * h.x;
            acc.y += exm * h.y;
            acc.z += exm * h.z;
            acc.w += exm * h.w;
        }
    }
    #pragma unroll
    for (int o = 16; o > 0; o >>= 1) {
        d0 += __shfl_xor_sync(0xffffffffu, d0, o);
        d1 += __shfl_xor_sync(0xffffffffu, d1, o);
    }
    float inv = 1.0f / ((lane < 16) ? d0 : d1);
    acc.x *= inv; acc.y *= inv; acc.z *= inv; acc.w *= inv;
    *(float4*)(g_agg0 + w * 128 + lane * 4) = acc;
}

// ---------------- K4: mean heads + b0, LN, ELU, GEMM W1, alphas --------------------
#define NPB4 32
__device__ __forceinline__ float2 gsum64x2(float a, float b, float* s4, int jj) {
    #pragma unroll
    for (int o = 16; o > 0; o >>= 1) {
        a += __shfl_xor_sync(0xffffffffu, a, o);
        b += __shfl_xor_sync(0xffffffffu, b, o);
    }
    if ((jj & 31) == 0) { s4[jj >> 5] = a; s4[2 + (jj >> 5)] = b; }
    __syncthreads();
    float2 r = make_float2(s4[0] + s4[1], s4[2] + s4[3]);
    __syncthreads();
    return r;
}

__global__ void __launch_bounds__(256) k4(const float* __restrict__ b0,
                   const float* __restrict__ lng, const float* __restrict__ lnb,
                   const float* __restrict__ W1, const float* __restrict__ a_s1,
                   const float* __restrict__ a_d1) {
    __shared__ __align__(16) float sX[4][64];
    __shared__ float sred[4][4];
    int tid = threadIdx.x;            // 256 threads: 4 groups of 64
    int gg = tid >> 6, jj = tid & 63;
    float wreg[64];
    #pragma unroll
    for (int t = 0; t < 64; ++t) wreg[t] = W1[t * 64 + jj];
    float aS = a_s1[jj], aD = a_d1[jj];
    float bb = b0[jj], g = lng[jj], be = lnb[jj];

    int base = blockIdx.x * NPB4;
    for (int it = 0; it < NPB4 / 4; ++it) {
        int n = base + it * 4 + gg;
        bool valid = (n < NN);
        int nn = valid ? n : 0;
        float y = 0.f;
        if (valid)
            y = 0.5f * (g_agg0[nn * 128 + jj] + g_agg0[nn * 128 + 64 + jj]) + bb;
        float2 r = gsum64x2(y, y * y, sred[gg], jj);
        float mu = r.x * (1.f / 64.f);
        float var = r.y * (1.f / 64.f) - mu * mu;
        float xn = (y - mu) * rsqrtf(var + 1e-5f) * g + be;
        float ev = xn > 0.f ? xn : expm1f(xn);
        sX[gg][jj] = ev;
        __syncthreads();
        float acc = 0.f;
        #pragma unroll
        for (int q = 0; q < 16; ++q) {
            float4 v = *(const float4*)&sX[gg][q * 4];
            acc += v.x * wreg[q * 4] + v.y * wreg[q * 4 + 1]
                 + v.z * wreg[q * 4 + 2] + v.w * wreg[q * 4 + 3];
        }
        float2 r2 = gsum64x2(acc * aS, acc * aD, sred[gg], jj);
        if (valid) {
            g_h1[n * 64 + jj] = acc;
            if (jj == 0) { g_as1[n] = r2.x; g_ad1[n] = r2.y; }
        }
        __syncthreads();
    }
}

// ---------------- kagg1: layer1 aggregation, warp per dst node, writes out --------
// out[n] = (sum_e ex_e * h1[src_e]) / den + b1
__global__ void __launch_bounds__(256) kagg1(float* __restrict__ out,
                                             const float* __restrict__ b1) {
    int w = (blockIdx.x * blockDim.x + threadIdx.x) >> 5;
    if (w >= NN) return;
    int lane = threadIdx.x & 31;
    int start = g_off[w], end = g_off[w + 1];
    float ad = g_ad1[w];
    float2 acc = make_float2(0.f, 0.f);
    float den = 0.f;
    for (int i = start; i < end; i += 32) {
        int idx = i + lane;
        int s = 0;
        float ex = 0.f;
        if (idx < end) {
            s = g_srcs[idx];
            float v = g_as1[s] + ad;
            v = v > 0.f ? v : 0.2f * v;
            ex = __expf(v);
        }
        den += ex;
        int cnt = min(32, end - i);
        for (int t = 0; t < cnt; ++t) {
            int sb = __shfl_sync(0xffffffffu, s, t);
            float eb = __shfl_sync(0xffffffffu, ex, t);
            const float2 h = *(const float2*)(g_h1 + sb * 64 + lane * 2);
            acc.x += eb * h.x;
            acc.y += eb * h.y;
        }
    }
    #pragma unroll
    for (int o = 16; o > 0; o >>= 1)
        den += __shfl_xor_sync(0xffffffffu, den, o);
    float inv = 1.0f / den;
    float2 bb = *(const float2*)(b1 + lane * 2);
    float2 r = make_float2(acc.x * inv + bb.x, acc.y * inv + bb.y);
    *(float2*)(out + w * 64 + lane * 2) = r;
}

// ---------------- launch -----------------------------------------------------------
extern "C" void kernel_launch(void* const* d_in, const int* in_sizes, int n_in,
                              void* d_out, int out_size) {
    const float* x      = (const float*)d_in[0];
    const int*   ei     = (const int*)  d_in[1];
    const float* emb    = (const float*)d_in[2];
    const float* W0     = (const float*)d_in[3];
    const float* a_src0 = (const float*)d_in[4];
    const float* a_dst0 = (const float*)d_in[5];
    const float* b0     = (const float*)d_in[6];
    const float* ln_g   = (const float*)d_in[7];
    const float* ln_b   = (const float*)d_in[8];
    const float* W1     = (const float*)d_in[9];
    const float* a_src1 = (const float*)d_in[10];
    const float* a_dst1 = (const float*)d_in[11];
    const float* b1     = (const float*)d_in[12];
    float* out = (float*)d_out;

    // CSR build (shared by both layers)
    kzero<<<(NN + 255) / 256, 256>>>();
    khist<<<(NE + 255) / 256, 256>>>(ei);
    kscan<<<1, 1024>>>();
    kscatter<<<(NE + 255) / 256, 256>>>(ei);
    // layer 0
    kprep<<<1, 192>>>(W0, a_src0, a_dst0);
    k1<<<(NN + K1_NPB - 1) / K1_NPB, 128>>>(x, emb, W0);
    kagg0<<<(NN * 32 + 255) / 256, 256>>>();
    // layer 1
    k4<<<(NN + NPB4 - 1) / NPB4, 256>>>(b0, ln_g, ln_b, W1, a_src1, a_dst1);
    kagg1<<<(NN * 32 + 255) / 256, 256>>>(out, b1);
}

// round 11
// speedup vs baseline: 1.5946x; 1.0149x over previous
#include <cuda_runtime.h>
#include <cuda_fp16.h>
#include <math.h>

// Problem constants
#define NN 50000
#define EE 800000
#define NE 850000      // EE + NN self loops
#define FIN 32
#define CDIM 16
#define DIN 48
#define CC 64
#define H0 2

// ---------------- device scratch (allocation-free rule: __device__ globals) --------
__device__ __half g_h0h[NN * 128];    // layer0 node features, fp16 [N,2,64]
__device__ float g_as0[NN * 2];
__device__ float g_ad0[NN * 2];
__device__ float g_agg0[NN * 128];    // normalized aggregated messages (fp32)
__device__ __half g_h1h[NN * 64];     // layer1 input features, fp16
__device__ float g_as1[NN];
__device__ float g_ad1[NN];
// CSR build scratch
__device__ int g_cnt[NN];
__device__ int g_off[NN + 1];
__device__ int g_cur[NN];
__device__ int g_srcs[NE];

// ---------------- CSR build: histogram of dst -------------------------------------
__global__ void khist(const int* __restrict__ ei) {
    int e = blockIdx.x * blockDim.x + threadIdx.x;
    if (e >= NE) return;
    int dst = (e < EE) ? ei[EE + e] : (e - EE);
    atomicAdd(&g_cnt[dst], 1);
}

// ---------------- CSR build: exclusive scan (single block, 1024 threads) ----------
__global__ void __launch_bounds__(1024) kscan() {
    __shared__ int spart[1024];
    const int CH = (NN + 1023) / 1024;   // 49
    int t = threadIdx.x;
    int base = t * CH;
    int sum = 0;
    for (int i = 0; i < CH; ++i) {
        int b = base + i;
        if (b < NN) sum += g_cnt[b];
    }
    spart[t] = sum;
    __syncthreads();
    for (int o = 1; o < 1024; o <<= 1) {
        int v = (t >= o) ? spart[t - o] : 0;
        __syncthreads();
        spart[t] += v;
        __syncthreads();
    }
    int run = spart[t] - sum;           // exclusive prefix of this thread's chunk
    for (int i = 0; i < CH; ++i) {
        int b = base + i;
        if (b < NN) {
            g_off[b] = run;
            g_cur[b] = run;
            run += g_cnt[b];
        }
    }
    if (t == 1023) g_off[NN] = spart[1023];
}

// ---------------- CSR build: scatter src ids --------------------------------------
__global__ void kscatter(const int* __restrict__ ei) {
    int e = blockIdx.x * blockDim.x + threadIdx.x;
    if (e >= NE) return;
    int src, dst;
    if (e < EE) { src = ei[e]; dst = ei[EE + e]; }
    else        { src = dst = e - EE; }
    int pos = atomicAdd(&g_cur[dst], 1);
    g_srcs[pos] = src;
}

// ---------------- K1: h0 = concat(base, emb[cid]) @ W0 ; folded as0/ad0 ------------
// Folded attention weights computed in-block (replaces kprep kernel).
#define K1_NPB 64
__global__ void __launch_bounds__(128) k1(const float* __restrict__ x,
                                          const float* __restrict__ emb,
                                          const float* __restrict__ W0,
                                          const float* __restrict__ aS0,
                                          const float* __restrict__ aD0) {
    __shared__ __align__(16) float sIn[8][52];
    __shared__ float swa[DIN * 4];
    int j = threadIdx.x;              // output column 0..127
    float wreg[48];
    #pragma unroll
    for (int k = 0; k < 48; ++k) wreg[k] = W0[k * 128 + j];
    // compute folded attention weights: swa[k*4+c] = sum_q W0[k,h*64+q]*a[h,q]
    for (int idx = j; idx < DIN * 4; idx += 128) {
        int kk = idx >> 2, c = idx & 3, h = c & 1;
        const float* a = (c < 2) ? aS0 : aD0;
        float s = 0.f;
        #pragma unroll
        for (int q = 0; q < 64; ++q) s += W0[kk * 128 + h * 64 + q] * a[h * 64 + q];
        swa[idx] = s;
    }

    int base = blockIdx.x * K1_NPB;
    for (int b = 0; b < K1_NPB / 8; ++b) {
        int n0 = base + b * 8;
        __syncthreads();
        #pragma unroll
        for (int r = 0; r < 3; ++r) {
            int s = j + r * 128;      // 0..383
            int m = s / 48, k = s % 48;
            int n = n0 + m;
            float v = 0.f;
            if (n < NN) {
                if (k < FIN) v = x[n * 33 + k];
                else {
                    int cid = (int)x[n * 33 + FIN];
                    v = emb[cid * CDIM + (k - FIN)];
                }
            }
            sIn[m][k] = v;
        }
        __syncthreads();

        float acc[8];
        #pragma unroll
        for (int m = 0; m < 8; ++m) {
            float a = 0.f;
            #pragma unroll
            for (int q = 0; q < 12; ++q) {
                float4 v = *(const float4*)&sIn[m][q * 4];
                a += v.x * wreg[q * 4] + v.y * wreg[q * 4 + 1]
                   + v.z * wreg[q * 4 + 2] + v.w * wreg[q * 4 + 3];
            }
            acc[m] = a;
        }
        #pragma unroll
        for (int m = 0; m < 8; ++m) {
            int n = n0 + m;
            if (n < NN) g_h0h[n * 128 + j] = __float2half(acc[m]);
        }
        if (j < 32) {
            int m = j >> 2, c = j & 3;
            int n = n0 + m;
            if (n < NN) {
                float s = 0.f;
                #pragma unroll
                for (int k = 0; k < 48; ++k) s += sIn[m][k] * swa[k * 4 + c];
                if (c < 2) g_as0[n * 2 + c] = s;
                else       g_ad0[n * 2 + (c & 1)] = s;
            }
        }
    }
}

// ---------------- kagg0: layer0 aggregation, warp per dst node --------------------
// acc = sum_e ex_e * h0[src_e]; write agg0 = acc / den (normalized, per head)
__global__ void __launch_bounds__(256) kagg0() {
    int w = (blockIdx.x * blockDim.x + threadIdx.x) >> 5;
    if (w >= NN) return;
    int lane = threadIdx.x & 31;
    int start = g_off[w], end = g_off[w + 1];
    float2 ad = *(const float2*)(g_ad0 + w * 2);
    float4 acc = make_float4(0.f, 0.f, 0.f, 0.f);
    float d0 = 0.f, d1 = 0.f;
    for (int i = start; i < end; i += 32) {
        int idx = i + lane;
        int s = 0;
        float ex0 = 0.f, ex1 = 0.f;
        if (idx < end) {
            s = g_srcs[idx];
            float2 a = *(const float2*)(g_as0 + s * 2);
            float v0 = a.x + ad.x;  v0 = v0 > 0.f ? v0 : 0.2f * v0;
            float v1 = a.y + ad.y;  v1 = v1 > 0.f ? v1 : 0.2f * v1;
            ex0 = __expf(v0);
            ex1 = __expf(v1);
        }
        d0 += ex0;
        d1 += ex1;
        int cnt = min(32, end - i);
        #pragma unroll 4
        for (int t = 0; t < cnt; ++t) {
            int sb = __shfl_sync(0xffffffffu, s, t);
            float e0 = __shfl_sync(0xffffffffu, ex0, t);
            float e1 = __shfl_sync(0xffffffffu, ex1, t);
            float exm = (lane < 16) ? e0 : e1;   // lanes 0-15: head0, 16-31: head1
            uint2 p = *(const uint2*)(g_h0h + sb * 128 + lane * 4);
            float2 f01 = __half22float2(*(__half2*)&p.x);
            float2 f23 = __half22float2(*(__half2*)&p.y);
            acc.x += exm * f01.x;
            acc.y += exm * f01.y;
            acc.z += exm * f23.x;
            acc.w += exm * f23.y;
        }
    }
    #pragma unroll
    for (int o = 16; o > 0; o >>= 1) {
        d0 += __shfl_xor_sync(0xffffffffu, d0, o);
        d1 += __shfl_xor_sync(0xffffffffu, d1, o);
    }
    float inv = 1.0f / ((lane < 16) ? d0 : d1);
    acc.x *= inv; acc.y *= inv; acc.z *= inv; acc.w *= inv;
    *(float4*)(g_agg0 + w * 128 + lane * 4) = acc;
}

// ---------------- K4: mean heads + b0, LN, ELU, GEMM W1, alphas --------------------
#define NPB4 32
__device__ __forceinline__ float2 gsum64x2(float a, float b, float* s4, int jj) {
    #pragma unroll
    for (int o = 16; o > 0; o >>= 1) {
        a += __shfl_xor_sync(0xffffffffu, a, o);
        b += __shfl_xor_sync(0xffffffffu, b, o);
    }
    if ((jj & 31) == 0) { s4[jj >> 5] = a; s4[2 + (jj >> 5)] = b; }
    __syncthreads();
    float2 r = make_float2(s4[0] + s4[1], s4[2] + s4[3]);
    __syncthreads();
    return r;
}

__global__ void __launch_bounds__(256) k4(const float* __restrict__ b0,
                   const float* __restrict__ lng, const float* __restrict__ lnb,
                   const float* __restrict__ W1, const float* __restrict__ a_s1,
                   const float* __restrict__ a_d1) {
    __shared__ __align__(16) float sX[4][64];
    __shared__ float sred[4][4];
    int tid = threadIdx.x;            // 256 threads: 4 groups of 64
    int gg = tid >> 6, jj = tid & 63;
    float wreg[64];
    #pragma unroll
    for (int t = 0; t < 64; ++t) wreg[t] = W1[t * 64 + jj];
    float aS = a_s1[jj], aD = a_d1[jj];
    float bb = b0[jj], g = lng[jj], be = lnb[jj];

    int base = blockIdx.x * NPB4;
    for (int it = 0; it < NPB4 / 4; ++it) {
        int n = base + it * 4 + gg;
        bool valid = (n < NN);
        int nn = valid ? n : 0;
        float y = 0.f;
        if (valid)
            y = 0.5f * (g_agg0[nn * 128 + jj] + g_agg0[nn * 128 + 64 + jj]) + bb;
        float2 r = gsum64x2(y, y * y, sred[gg], jj);
        float mu = r.x * (1.f / 64.f);
        float var = r.y * (1.f / 64.f) - mu * mu;
        float xn = (y - mu) * rsqrtf(var + 1e-5f) * g + be;
        float ev = xn > 0.f ? xn : expm1f(xn);
        sX[gg][jj] = ev;
        __syncthreads();
        float acc = 0.f;
        #pragma unroll
        for (int q = 0; q < 16; ++q) {
            float4 v = *(const float4*)&sX[gg][q * 4];
            acc += v.x * wreg[q * 4] + v.y * wreg[q * 4 + 1]
                 + v.z * wreg[q * 4 + 2] + v.w * wreg[q * 4 + 3];
        }
        float2 r2 = gsum64x2(acc * aS, acc * aD, sred[gg], jj);
        if (valid) {
            g_h1h[n * 64 + jj] = __float2half(acc);
            if (jj == 0) { g_as1[n] = r2.x; g_ad1[n] = r2.y; }
        }
        __syncthreads();
    }
}

// ---------------- kagg1: layer1 aggregation, warp per dst node, writes out --------
// out[n] = (sum_e ex_e * h1[src_e]) / den + b1
__global__ void __launch_bounds__(256) kagg1(float* __restrict__ out,
                                             const float* __restrict__ b1) {
    int w = (blockIdx.x * blockDim.x + threadIdx.x) >> 5;
    if (w >= NN) return;
    int lane = threadIdx.x & 31;
    int start = g_off[w], end = g_off[w + 1];
    float ad = g_ad1[w];
    float2 acc = make_float2(0.f, 0.f);
    float den = 0.f;
    for (int i = start; i < end; i += 32) {
        int idx = i + lane;
        int s = 0;
        float ex = 0.f;
        if (idx < end) {
            s = g_srcs[idx];
            float v = g_as1[s] + ad;
            v = v > 0.f ? v : 0.2f * v;
            ex = __expf(v);
        }
        den += ex;
        int cnt = min(32, end - i);
        #pragma unroll 4
        for (int t = 0; t < cnt; ++t) {
            int sb = __shfl_sync(0xffffffffu, s, t);
            float eb = __shfl_sync(0xffffffffu, ex, t);
            __half2 hp = *(const __half2*)(g_h1h + sb * 64 + lane * 2);
            float2 f = __half22float2(hp);
            acc.x += eb * f.x;
            acc.y += eb * f.y;
        }
    }
    #pragma unroll
    for (int o = 16; o > 0; o >>= 1)
        den += __shfl_xor_sync(0xffffffffu, den, o);
    float inv = 1.0f / den;
    float2 bb = *(const float2*)(b1 + lane * 2);
    float2 r = make_float2(acc.x * inv + bb.x, acc.y * inv + bb.y);
    *(float2*)(out + w * 64 + lane * 2) = r;
}

// ---------------- launch -----------------------------------------------------------
extern "C" void kernel_launch(void* const* d_in, const int* in_sizes, int n_in,
                              void* d_out, int out_size) {
    const float* x      = (const float*)d_in[0];
    const int*   ei     = (const int*)  d_in[1];
    const float* emb    = (const float*)d_in[2];
    const float* W0     = (const float*)d_in[3];
    const float* a_src0 = (const float*)d_in[4];
    const float* a_dst0 = (const float*)d_in[5];
    const float* b0     = (const float*)d_in[6];
    const float* ln_g   = (const float*)d_in[7];
    const float* ln_b   = (const float*)d_in[8];
    const float* W1     = (const float*)d_in[9];
    const float* a_src1 = (const float*)d_in[10];
    const float* a_dst1 = (const float*)d_in[11];
    const float* b1     = (const float*)d_in[12];
    float* out = (float*)d_out;

    // CSR build (shared by both layers)
    void* cnt_addr = nullptr;
    cudaGetSymbolAddress(&cnt_addr, g_cnt);
    cudaMemsetAsync(cnt_addr, 0, NN * sizeof(int));
    khist<<<(NE + 255) / 256, 256>>>(ei);
    kscan<<<1, 1024>>>();
    kscatter<<<(NE + 255) / 256, 256>>>(ei);
    // layer 0
    k1<<<(NN + K1_NPB - 1) / K1_NPB, 128>>>(x, emb, W0, a_src0, a_dst0);
    kagg0<<<(NN * 32 + 255) / 256, 256>>>();
    // layer 1
    k4<<<(NN + NPB4 - 1) / NPB4, 256>>>(b0, ln_g, ln_b, W1, a_src1, a_dst1);
    kagg1<<<(NN * 32 + 255) / 256, 256>>>(out, b1);
}